// round 1
// baseline (speedup 1.0000x reference)
#include <cuda_runtime.h>
#include <cuda_bf16.h>
#include <math.h>

// Problem constants
#define B_SZ   1024
#define F_NUM  64
#define D_IN   256
#define D_OUT  256
#define H_NUM  8
#define DH     32
#define LN_EPS 1e-5f

// Scratch: q, k, v, attn_out  — each [B, F, 256] fp32 = 64 MB
__device__ float g_q[B_SZ * F_NUM * D_OUT];
__device__ float g_k[B_SZ * F_NUM * D_OUT];
__device__ float g_v[B_SZ * F_NUM * D_OUT];
__device__ float g_attn[B_SZ * F_NUM * D_OUT];

// ---------------------------------------------------------------------------
// Stage 1: per-f QKV GEMMs.
// C[b, f*256 + w] = sum_d theta[b, f, d] * W[f][d, w]   for W in {Q,K,V}
// Batched tiled GEMM: M=1024 (b), N=256 (w), K=256 (d), batch = f*3 + which.
// BM=64, BN=64, BK=16, 256 threads, 4x4 microtile.
// ---------------------------------------------------------------------------
__global__ __launch_bounds__(256) void qkv_gemm_kernel(
    const float* __restrict__ theta,
    const float* __restrict__ Qw,
    const float* __restrict__ Kw,
    const float* __restrict__ Vw)
{
    const int batch = blockIdx.z;
    const int f     = batch / 3;
    const int which = batch % 3;
    const float* W = (which == 0 ? Qw : (which == 1 ? Kw : Vw)) + (size_t)f * D_IN * D_OUT;
    float* C = (which == 0 ? g_q : (which == 1 ? g_k : g_v));

    const int m0 = blockIdx.x * 64;   // b tile
    const int n0 = blockIdx.y * 64;   // w tile

    __shared__ float As[64][16];      // [row][k]
    __shared__ float Bs[16][64];      // [k][n]

    const int tid = threadIdx.x;
    const int tx = tid & 15;          // 0..15 -> 4 cols each
    const int ty = tid >> 4;          // 0..15 -> 4 rows each

    float acc[4][4];
#pragma unroll
    for (int j = 0; j < 4; j++)
#pragma unroll
        for (int i = 0; i < 4; i++) acc[j][i] = 0.f;

    const float* Aptr = theta + (size_t)f * D_IN;  // A[b][d] = Aptr[b*16384 + d]

    const int la_c = tid & 15;        // A load: col in tile
    const int la_r = tid >> 4;        // A load: base row
    const int lb_n = tid & 63;        // B load: n in tile
    const int lb_k = tid >> 6;        // B load: base k

    for (int k0 = 0; k0 < D_IN; k0 += 16) {
#pragma unroll
        for (int p = 0; p < 4; p++) {
            As[la_r + 16 * p][la_c] =
                Aptr[(size_t)(m0 + la_r + 16 * p) * (F_NUM * D_IN) + k0 + la_c];
        }
#pragma unroll
        for (int p = 0; p < 4; p++) {
            Bs[lb_k + 4 * p][lb_n] = W[(size_t)(k0 + lb_k + 4 * p) * D_OUT + n0 + lb_n];
        }
        __syncthreads();

#pragma unroll
        for (int kk = 0; kk < 16; kk++) {
            float4 bv = *reinterpret_cast<const float4*>(&Bs[kk][tx * 4]);
            float bb[4] = {bv.x, bv.y, bv.z, bv.w};
            float aa[4];
#pragma unroll
            for (int j = 0; j < 4; j++) aa[j] = As[ty * 4 + j][kk];
#pragma unroll
            for (int j = 0; j < 4; j++)
#pragma unroll
                for (int i = 0; i < 4; i++) acc[j][i] = fmaf(aa[j], bb[i], acc[j][i]);
        }
        __syncthreads();
    }

#pragma unroll
    for (int j = 0; j < 4; j++) {
        const size_t b = (size_t)(m0 + ty * 4 + j);
        float4 v4 = make_float4(acc[j][0], acc[j][1], acc[j][2], acc[j][3]);
        *reinterpret_cast<float4*>(&C[b * (F_NUM * D_OUT) + (size_t)f * D_OUT + n0 + tx * 4]) = v4;
    }
}

// ---------------------------------------------------------------------------
// Stage 2: attention per (b, h). F=64, dh=32 tiles live entirely in smem.
// logits[f,g] = sum_e cos(q)*rw*cos(k) + sin(q)*rw*sin(k); S = sigmoid;
// attn[f,d] = sum_g S[f,g] * v[g,d]
// smem padded to 33 floats/row for conflict-free transposed access.
// ---------------------------------------------------------------------------
#define S2_PAD 33
#define S2_SMEM_BYTES ((5 * 64 * S2_PAD + 64 * 64) * 4)

__global__ __launch_bounds__(256) void attn_kernel(const float* __restrict__ rot_w)
{
    const int b = blockIdx.x >> 3;
    const int h = blockIdx.x & 7;

    extern __shared__ float sm[];
    float* cq = sm;                    // [64][33]
    float* sq = cq + 64 * S2_PAD;
    float* ck = sq + 64 * S2_PAD;
    float* sk = ck + 64 * S2_PAD;
    float* vv = sk + 64 * S2_PAD;
    float* S  = vv + 64 * S2_PAD;      // [64][64]

    const int tid = threadIdx.x;
    const size_t base = (size_t)b * (F_NUM * D_OUT) + (size_t)h * DH;

    // Load q, k, v; compute trig.
    {
        const int e  = tid & 31;
        const int f0 = tid >> 5;       // 0..7
        const float rw = rot_w[e];
#pragma unroll
        for (int p = 0; p < 8; p++) {
            const int f = f0 + 8 * p;
            const size_t idx = base + (size_t)f * D_OUT + e;
            const float qv = g_q[idx];
            const float kv = g_k[idx];
            float sqv, cqv, skv, ckv;
            sincosf(qv, &sqv, &cqv);
            sincosf(kv, &skv, &ckv);
            cq[f * S2_PAD + e] = cqv * rw;
            sq[f * S2_PAD + e] = sqv * rw;
            ck[f * S2_PAD + e] = ckv;
            sk[f * S2_PAD + e] = skv;
            vv[f * S2_PAD + e] = g_v[idx];
        }
    }
    __syncthreads();

    // logits + sigmoid -> S
    {
        const int g   = tid & 63;
        const int fq0 = tid >> 6;      // 0..3
#pragma unroll 4
        for (int p = 0; p < 16; p++) {
            const int f = fq0 + 4 * p;
            float acc = 0.f;
#pragma unroll
            for (int e = 0; e < 32; e++) {
                acc = fmaf(cq[f * S2_PAD + e], ck[g * S2_PAD + e], acc);
                acc = fmaf(sq[f * S2_PAD + e], sk[g * S2_PAD + e], acc);
            }
            S[f * 64 + g] = 1.f / (1.f + __expf(-acc));
        }
    }
    __syncthreads();

    // attn out = S @ v
    {
        const int d  = tid & 31;
        const int f0 = tid >> 5;
#pragma unroll
        for (int p = 0; p < 8; p++) {
            const int f = f0 + 8 * p;
            float acc = 0.f;
#pragma unroll
            for (int g = 0; g < 64; g++) {
                acc = fmaf(S[f * 64 + g], vv[g * S2_PAD + d], acc);
            }
            g_attn[base + (size_t)f * D_OUT + d] = acc;
        }
    }
}

// ---------------------------------------------------------------------------
// Stage 3: fused linear + residual-add + LayerNorm.
// res[row, w] = attn[row, w] + sum_d theta[row, d] * W_lin[w, d]
// then LN over w (256) with gamma/beta.
// CTA: 32 rows x all 256 cols. Warp = 4 rows -> LN via shfl reduce.
// ---------------------------------------------------------------------------
__global__ __launch_bounds__(256) void lin_ln_kernel(
    const float* __restrict__ theta,
    const float* __restrict__ W_lin,
    const float* __restrict__ gamma,
    const float* __restrict__ beta,
    float* __restrict__ out)
{
    __shared__ float As[32][16];       // [row][k]
    __shared__ float Bs[16][256];      // [k][w]  (W_lin transposed on load)

    const int row0 = blockIdx.x * 32;
    const int tid = threadIdx.x;
    const int tx = tid & 31;           // lane: cols tx*8 .. tx*8+7
    const int ty = tid >> 5;           // warp: rows ty*4 .. ty*4+3

    float acc[4][8];
#pragma unroll
    for (int j = 0; j < 4; j++)
#pragma unroll
        for (int i = 0; i < 8; i++) acc[j][i] = 0.f;

    const int la_r = tid >> 3;         // 0..31
    const int la_c = (tid & 7) * 2;    // 0..14

    for (int k0 = 0; k0 < D_IN; k0 += 16) {
        {
            float2 t2 = *reinterpret_cast<const float2*>(
                &theta[(size_t)(row0 + la_r) * D_IN + k0 + la_c]);
            As[la_r][la_c]     = t2.x;
            As[la_r][la_c + 1] = t2.y;
        }
        {
#pragma unroll
            for (int p = 0; p < 4; p++) {
                float4 w4 = *reinterpret_cast<const float4*>(
                    &W_lin[(size_t)tid * D_IN + k0 + p * 4]);
                Bs[p * 4 + 0][tid] = w4.x;
                Bs[p * 4 + 1][tid] = w4.y;
                Bs[p * 4 + 2][tid] = w4.z;
                Bs[p * 4 + 3][tid] = w4.w;
            }
        }
        __syncthreads();

#pragma unroll
        for (int kk = 0; kk < 16; kk++) {
            float4 b0 = *reinterpret_cast<const float4*>(&Bs[kk][tx * 8]);
            float4 b1 = *reinterpret_cast<const float4*>(&Bs[kk][tx * 8 + 4]);
            float bb[8] = {b0.x, b0.y, b0.z, b0.w, b1.x, b1.y, b1.z, b1.w};
#pragma unroll
            for (int j = 0; j < 4; j++) {
                const float a = As[ty * 4 + j][kk];
#pragma unroll
                for (int i = 0; i < 8; i++) acc[j][i] = fmaf(a, bb[i], acc[j][i]);
            }
        }
        __syncthreads();
    }

    float g8[8], b8[8];
#pragma unroll
    for (int i = 0; i < 8; i++) {
        g8[i] = gamma[tx * 8 + i];
        b8[i] = beta[tx * 8 + i];
    }

#pragma unroll
    for (int j = 0; j < 4; j++) {
        const size_t row = (size_t)(row0 + ty * 4 + j);
        float4 a0 = *reinterpret_cast<const float4*>(&g_attn[row * D_OUT + tx * 8]);
        float4 a1 = *reinterpret_cast<const float4*>(&g_attn[row * D_OUT + tx * 8 + 4]);
        float v[8];
        v[0] = acc[j][0] + a0.x; v[1] = acc[j][1] + a0.y;
        v[2] = acc[j][2] + a0.z; v[3] = acc[j][3] + a0.w;
        v[4] = acc[j][4] + a1.x; v[5] = acc[j][5] + a1.y;
        v[6] = acc[j][6] + a1.z; v[7] = acc[j][7] + a1.w;

        float s = 0.f, ss = 0.f;
#pragma unroll
        for (int i = 0; i < 8; i++) { s += v[i]; ss = fmaf(v[i], v[i], ss); }
#pragma unroll
        for (int o = 16; o > 0; o >>= 1) {
            s  += __shfl_xor_sync(0xffffffffu, s,  o);
            ss += __shfl_xor_sync(0xffffffffu, ss, o);
        }
        const float mu  = s * (1.f / 256.f);
        const float var = ss * (1.f / 256.f) - mu * mu;
        const float inv = rsqrtf(var + LN_EPS);

        float o8[8];
#pragma unroll
        for (int i = 0; i < 8; i++) o8[i] = fmaf((v[i] - mu) * inv, g8[i], b8[i]);

        *reinterpret_cast<float4*>(&out[row * D_OUT + tx * 8]) =
            make_float4(o8[0], o8[1], o8[2], o8[3]);
        *reinterpret_cast<float4*>(&out[row * D_OUT + tx * 8 + 4]) =
            make_float4(o8[4], o8[5], o8[6], o8[7]);
    }
}

// ---------------------------------------------------------------------------
// Launch
// ---------------------------------------------------------------------------
extern "C" void kernel_launch(void* const* d_in, const int* in_sizes, int n_in,
                              void* d_out, int out_size)
{
    const float* theta  = (const float*)d_in[0];
    const float* Qw     = (const float*)d_in[1];
    const float* Kw     = (const float*)d_in[2];
    const float* Vw     = (const float*)d_in[3];
    const float* W_lin  = (const float*)d_in[4];
    const float* rot_w  = (const float*)d_in[5];
    const float* gammap = (const float*)d_in[6];
    const float* betap  = (const float*)d_in[7];
    float* out = (float*)d_out;

    cudaFuncSetAttribute(attn_kernel,
                         cudaFuncAttributeMaxDynamicSharedMemorySize, S2_SMEM_BYTES);

    // Stage 1: QKV GEMMs
    qkv_gemm_kernel<<<dim3(B_SZ / 64, D_OUT / 64, F_NUM * 3), 256>>>(theta, Qw, Kw, Vw);
    // Stage 2: attention
    attn_kernel<<<B_SZ * H_NUM, 256, S2_SMEM_BYTES>>>(rot_w);
    // Stage 3: linear + residual + LayerNorm
    lin_ln_kernel<<<(B_SZ * F_NUM) / 32, 256>>>(theta, W_lin, gammap, betap, out);
}

// round 9
// speedup vs baseline: 1.7156x; 1.7156x over previous
#include <cuda_runtime.h>
#include <cuda_bf16.h>
#include <math.h>
#include <stdint.h>

// Problem constants
#define B_SZ   1024
#define F_NUM  64
#define D_IN   256
#define D_OUT  256
#define H_NUM  8
#define DH     32
#define LN_EPS 1e-5f

// ---------------------------------------------------------------------------
// Device scratch
// ---------------------------------------------------------------------------
__device__ float g_q[B_SZ * F_NUM * D_OUT];
__device__ float g_k[B_SZ * F_NUM * D_OUT];
__device__ float g_v[B_SZ * F_NUM * D_OUT];
__device__ float g_attn[B_SZ * F_NUM * D_OUT];
__device__ float g_res[B_SZ * F_NUM * D_OUT];

// Split-precision bf16 operands.
// theta, f-major [64][1024][256] (stage 1 A)
__device__ __nv_bfloat16 g_Ah[(size_t)F_NUM * B_SZ * D_IN];
__device__ __nv_bfloat16 g_Al[(size_t)F_NUM * B_SZ * D_IN];
// theta, natural row-major [65536][256] (stage 3 A)
__device__ __nv_bfloat16 g_Th[(size_t)B_SZ * F_NUM * D_IN];
__device__ __nv_bfloat16 g_Tl[(size_t)B_SZ * F_NUM * D_IN];
// concat(Q,K,V): [64][768][256], [N][K] K-major (B[n][k] = W[k][n])
__device__ __nv_bfloat16 g_Bh[(size_t)F_NUM * 3 * D_OUT * D_IN];
__device__ __nv_bfloat16 g_Bl[(size_t)F_NUM * 3 * D_OUT * D_IN];
// W_lin: already [out=w][in=d] = [N][K] K-major; elementwise split.
__device__ __nv_bfloat16 g_Wh[(size_t)D_OUT * D_IN];
__device__ __nv_bfloat16 g_Wl[(size_t)D_OUT * D_IN];

// ---------------------------------------------------------------------------
// Warp-MMA helpers (generic PTX, sm_80-era: valid at compute_103 target)
// ---------------------------------------------------------------------------
__device__ __forceinline__ uint32_t smem_u32(const void* p) {
    uint32_t a;
    asm("{ .reg .u64 t; cvta.to.shared.u64 t, %1; cvt.u32.u64 %0, t; }" : "=r"(a) : "l"(p));
    return a;
}
__device__ __forceinline__ void ldmx4(uint32_t* r, uint32_t addr) {
    asm volatile("ldmatrix.sync.aligned.m8n8.x4.shared.b16 {%0,%1,%2,%3}, [%4];"
                 : "=r"(r[0]), "=r"(r[1]), "=r"(r[2]), "=r"(r[3]) : "r"(addr));
}
__device__ __forceinline__ void mma16816(float* d, const uint32_t* a, const uint32_t* b) {
    asm volatile("mma.sync.aligned.m16n8k16.row.col.f32.bf16.bf16.f32 "
                 "{%0,%1,%2,%3}, {%4,%5,%6,%7}, {%8,%9}, {%0,%1,%2,%3};"
                 : "+f"(d[0]), "+f"(d[1]), "+f"(d[2]), "+f"(d[3])
                 : "r"(a[0]), "r"(a[1]), "r"(a[2]), "r"(a[3]), "r"(b[0]), "r"(b[1]));
}

#define PITCH 40   // bf16 elems per smem row (80 B) — conflict-free, 16B-aligned rows

// ---------------------------------------------------------------------------
// Stage 0a: split theta -> f-major hi/lo AND natural-layout hi/lo
// ---------------------------------------------------------------------------
__global__ __launch_bounds__(256) void split_theta_kernel(const float* __restrict__ theta)
{
    const size_t idx  = (size_t)blockIdx.x * blockDim.x + threadIdx.x;  // float4 index
    const size_t elem = idx * 4;
    const int d = (int)(elem & 255);
    const int f = (int)((elem >> 8) & 63);
    const int b = (int)(elem >> 14);
    float4 t4 = *reinterpret_cast<const float4*>(theta + elem);
    float xs[4] = {t4.x, t4.y, t4.z, t4.w};
    __nv_bfloat16 hi[4], lo[4];
#pragma unroll
    for (int i = 0; i < 4; i++) {
        hi[i] = __float2bfloat16(xs[i]);
        lo[i] = __float2bfloat16(xs[i] - __bfloat162float(hi[i]));
    }
    const size_t o = ((size_t)f << 18) + ((size_t)b << 8) + d;   // f-major
    *reinterpret_cast<uint2*>(&g_Ah[o]) = *reinterpret_cast<uint2*>(hi);
    *reinterpret_cast<uint2*>(&g_Al[o]) = *reinterpret_cast<uint2*>(lo);
    *reinterpret_cast<uint2*>(&g_Th[elem]) = *reinterpret_cast<uint2*>(hi);  // natural
    *reinterpret_cast<uint2*>(&g_Tl[elem]) = *reinterpret_cast<uint2*>(lo);
}

// ---------------------------------------------------------------------------
// Stage 0b: transpose + split QKV weights: W[f][d][w] -> B[f][which*256+w][d]
// ---------------------------------------------------------------------------
__global__ __launch_bounds__(256) void split_weights_kernel(
    const float* __restrict__ Qw, const float* __restrict__ Kw, const float* __restrict__ Vw)
{
    __shared__ float tile[32][33];
    const int f = blockIdx.z;
    const int which = blockIdx.y;
    const int d0 = (blockIdx.x >> 3) * 32;
    const int w0 = (blockIdx.x & 7) * 32;
    const float* W = (which == 0 ? Qw : (which == 1 ? Kw : Vw)) + (size_t)f * D_IN * D_OUT;

    const int c = threadIdx.x & 31;
    const int r0 = threadIdx.x >> 5;
#pragma unroll
    for (int i = 0; i < 4; i++) {
        const int r = r0 + 8 * i;
        tile[r][c] = W[(size_t)(d0 + r) * D_OUT + w0 + c];
    }
    __syncthreads();

    const size_t outbase = (size_t)f * (3 * D_OUT * D_IN) + (size_t)(which * 256 + w0) * D_IN + d0;
#pragma unroll
    for (int i = 0; i < 4; i++) {
        const int wr = r0 + 8 * i;     // output row (w)
        const int dc = c;              // output col (d)
        const float x = tile[dc][wr];
        const __nv_bfloat16 hi = __float2bfloat16(x);
        const __nv_bfloat16 lo = __float2bfloat16(x - __bfloat162float(hi));
        g_Bh[outbase + (size_t)wr * D_IN + dc] = hi;
        g_Bl[outbase + (size_t)wr * D_IN + dc] = lo;
    }
}

// ---------------------------------------------------------------------------
// Stage 0c: split W_lin elementwise (already [N][K] K-major)
// ---------------------------------------------------------------------------
__global__ __launch_bounds__(256) void split_wlin_kernel(const float* __restrict__ W_lin)
{
    const int i = blockIdx.x * blockDim.x + threadIdx.x;
    const float x = W_lin[i];
    const __nv_bfloat16 hi = __float2bfloat16(x);
    g_Wh[i] = hi;
    g_Wl[i] = __float2bfloat16(x - __bfloat162float(hi));
}

// ---------------------------------------------------------------------------
// Shared warp-MMA mainloop (CTA 128x128, BK=32, 8 warps, warp tile 64x32).
// Computes acc = Ah*Bh + Ah*Bl + Al*Bh over K=256.
// ---------------------------------------------------------------------------
struct SmemTiles {
    __nv_bfloat16 Ah[128 * PITCH];
    __nv_bfloat16 Al[128 * PITCH];
    __nv_bfloat16 Bh[128 * PITCH];
    __nv_bfloat16 Bl[128 * PITCH];
};

__device__ __forceinline__ void mma_mainloop(
    SmemTiles& sm,
    const __nv_bfloat16* __restrict__ gAh, const __nv_bfloat16* __restrict__ gAl,
    const __nv_bfloat16* __restrict__ gBh, const __nv_bfloat16* __restrict__ gBl,
    float acc[4][4][4])
{
    const int tid = threadIdx.x;
    const int wid = tid >> 5;
    const int lane = tid & 31;
    const int warp_m = wid & 1;        // 2 warps over M
    const int warp_n = wid >> 1;       // 4 warps over N

    // Per-thread load decode: 4 chunks of 4 bf16 (8B) per operand.
    int lrow[4], lc4[4];
#pragma unroll
    for (int i = 0; i < 4; i++) {
        const int idx = tid + 256 * i;
        lrow[i] = idx >> 3;
        lc4[i]  = idx & 7;
    }

    // ldmatrix address precompute (within-warp lane decode)
    const int a_row = warp_m * 64 + (lane & 15);
    const int a_kh  = (lane >> 4) << 3;
    const int b_n   = warp_n * 32 + (lane & 7) + ((lane >> 4) << 3);
    const int b_kh  = ((lane >> 3) & 1) << 3;

    uint2 pf[4][4];
    // Prefetch kt = 0
#pragma unroll
    for (int i = 0; i < 4; i++) {
        const size_t off = (size_t)lrow[i] * 256 + lc4[i] * 4;
        pf[0][i] = *reinterpret_cast<const uint2*>(gAh + off);
        pf[1][i] = *reinterpret_cast<const uint2*>(gAl + off);
        pf[2][i] = *reinterpret_cast<const uint2*>(gBh + off);
        pf[3][i] = *reinterpret_cast<const uint2*>(gBl + off);
    }

    for (int kt = 0; kt < 8; kt++) {
#pragma unroll
        for (int i = 0; i < 4; i++) {
            const int s = lrow[i] * PITCH + lc4[i] * 4;
            *reinterpret_cast<uint2*>(&sm.Ah[s]) = pf[0][i];
            *reinterpret_cast<uint2*>(&sm.Al[s]) = pf[1][i];
            *reinterpret_cast<uint2*>(&sm.Bh[s]) = pf[2][i];
            *reinterpret_cast<uint2*>(&sm.Bl[s]) = pf[3][i];
        }
        __syncthreads();

        if (kt < 7) {
            const int k0 = (kt + 1) * 32;
#pragma unroll
            for (int i = 0; i < 4; i++) {
                const size_t off = (size_t)lrow[i] * 256 + k0 + lc4[i] * 4;
                pf[0][i] = *reinterpret_cast<const uint2*>(gAh + off);
                pf[1][i] = *reinterpret_cast<const uint2*>(gAl + off);
                pf[2][i] = *reinterpret_cast<const uint2*>(gBh + off);
                pf[3][i] = *reinterpret_cast<const uint2*>(gBl + off);
            }
        }

#pragma unroll
        for (int kh = 0; kh < 2; kh++) {
            const int k16 = kh * 16;
            // B fragments: 4 n-frags of 8, hi and lo (2 ldmatrix.x4 each)
            uint32_t bh[4][2], bl[4][2];
#pragma unroll
            for (int p = 0; p < 2; p++) {
                uint32_t r[4];
                const int nrow = b_n + p * 16;
                ldmx4(r, smem_u32(&sm.Bh[nrow * PITCH + k16 + b_kh]));
                bh[2 * p][0] = r[0]; bh[2 * p][1] = r[1];
                bh[2 * p + 1][0] = r[2]; bh[2 * p + 1][1] = r[3];
                ldmx4(r, smem_u32(&sm.Bl[nrow * PITCH + k16 + b_kh]));
                bl[2 * p][0] = r[0]; bl[2 * p][1] = r[1];
                bl[2 * p + 1][0] = r[2]; bl[2 * p + 1][1] = r[3];
            }
#pragma unroll
            for (int mf = 0; mf < 4; mf++) {
                uint32_t ah[4], al[4];
                const int arow = a_row + mf * 16;
                ldmx4(ah, smem_u32(&sm.Ah[arow * PITCH + k16 + a_kh]));
                ldmx4(al, smem_u32(&sm.Al[arow * PITCH + k16 + a_kh]));
#pragma unroll
                for (int nf = 0; nf < 4; nf++) {
                    mma16816(acc[mf][nf], ah, bh[nf]);
                    mma16816(acc[mf][nf], ah, bl[nf]);
                    mma16816(acc[mf][nf], al, bh[nf]);
                }
            }
        }
        __syncthreads();
    }
}

// ---------------------------------------------------------------------------
// Stage 1: QKV GEMM. grid (8, 6, 64): m-tile, n-tile (N=768), f.
// ---------------------------------------------------------------------------
__global__ __launch_bounds__(256) void qkv_mma_kernel()
{
    __shared__ __align__(16) SmemTiles sm;
    const int lane = threadIdx.x & 31;
    const int wid  = threadIdx.x >> 5;
    const int warp_m = wid & 1, warp_n = wid >> 1;
    const int f  = blockIdx.z;
    const int m0 = blockIdx.x * 128;
    const int n0 = blockIdx.y * 128;

    const __nv_bfloat16* gAh = g_Ah + ((size_t)f << 18) + ((size_t)m0 << 8);
    const __nv_bfloat16* gAl = g_Al + ((size_t)f << 18) + ((size_t)m0 << 8);
    const __nv_bfloat16* gBh = g_Bh + (size_t)f * (3 * D_OUT * D_IN) + ((size_t)n0 << 8);
    const __nv_bfloat16* gBl = g_Bl + (size_t)f * (3 * D_OUT * D_IN) + ((size_t)n0 << 8);

    float acc[4][4][4];
#pragma unroll
    for (int a = 0; a < 4; a++)
#pragma unroll
        for (int b = 0; b < 4; b++)
#pragma unroll
            for (int c = 0; c < 4; c++) acc[a][b][c] = 0.f;

    mma_mainloop(sm, gAh, gAl, gBh, gBl, acc);

    // Epilogue: direct stores into g_q / g_k / g_v
    const int gn = n0 + warp_n * 32;
    const int which = gn >> 8;
    float* C = (which == 0 ? g_q : (which == 1 ? g_k : g_v));
    const int wloc = gn & 255;
#pragma unroll
    for (int mf = 0; mf < 4; mf++) {
        const int row = m0 + warp_m * 64 + mf * 16 + (lane >> 2);
#pragma unroll
        for (int nf = 0; nf < 4; nf++) {
            const int c = wloc + nf * 8 + (lane & 3) * 2;
            const size_t o = (size_t)row * (F_NUM * D_OUT) + f * 256 + c;
            *reinterpret_cast<float2*>(&C[o]) = make_float2(acc[mf][nf][0], acc[mf][nf][1]);
            *reinterpret_cast<float2*>(&C[o + (size_t)8 * (F_NUM * D_OUT)]) =
                make_float2(acc[mf][nf][2], acc[mf][nf][3]);
        }
    }
}

// ---------------------------------------------------------------------------
// Stage 3a: linear GEMM res = theta @ W_lin^T. grid (512, 2).
// ---------------------------------------------------------------------------
__global__ __launch_bounds__(256) void lin_mma_kernel()
{
    __shared__ __align__(16) SmemTiles sm;
    const int lane = threadIdx.x & 31;
    const int wid  = threadIdx.x >> 5;
    const int warp_m = wid & 1, warp_n = wid >> 1;
    const int m0 = blockIdx.x * 128;
    const int n0 = blockIdx.y * 128;

    const __nv_bfloat16* gAh = g_Th + ((size_t)m0 << 8);
    const __nv_bfloat16* gAl = g_Tl + ((size_t)m0 << 8);
    const __nv_bfloat16* gBh = g_Wh + ((size_t)n0 << 8);
    const __nv_bfloat16* gBl = g_Wl + ((size_t)n0 << 8);

    float acc[4][4][4];
#pragma unroll
    for (int a = 0; a < 4; a++)
#pragma unroll
        for (int b = 0; b < 4; b++)
#pragma unroll
            for (int c = 0; c < 4; c++) acc[a][b][c] = 0.f;

    mma_mainloop(sm, gAh, gAl, gBh, gBl, acc);

#pragma unroll
    for (int mf = 0; mf < 4; mf++) {
        const int row = m0 + warp_m * 64 + mf * 16 + (lane >> 2);
#pragma unroll
        for (int nf = 0; nf < 4; nf++) {
            const int c = n0 + warp_n * 32 + nf * 8 + (lane & 3) * 2;
            const size_t o = (size_t)row * D_OUT + c;
            *reinterpret_cast<float2*>(&g_res[o]) = make_float2(acc[mf][nf][0], acc[mf][nf][1]);
            *reinterpret_cast<float2*>(&g_res[o + (size_t)8 * D_OUT]) =
                make_float2(acc[mf][nf][2], acc[mf][nf][3]);
        }
    }
}

// ---------------------------------------------------------------------------
// Stage 2: attention per (b, h). (unchanged from passing R1 kernel)
// ---------------------------------------------------------------------------
#define S2_PAD 33
#define S2_SMEM_BYTES ((5 * 64 * S2_PAD + 64 * 64) * 4)

__global__ __launch_bounds__(256) void attn_kernel(const float* __restrict__ rot_w)
{
    const int b = blockIdx.x >> 3;
    const int h = blockIdx.x & 7;

    extern __shared__ float sm2[];
    float* cq = sm2;
    float* sq = cq + 64 * S2_PAD;
    float* ck = sq + 64 * S2_PAD;
    float* sk = ck + 64 * S2_PAD;
    float* vv = sk + 64 * S2_PAD;
    float* S  = vv + 64 * S2_PAD;

    const int tid = threadIdx.x;
    const size_t base = (size_t)b * (F_NUM * D_OUT) + (size_t)h * DH;

    {
        const int e  = tid & 31;
        const int f0 = tid >> 5;
        const float rw = rot_w[e];
#pragma unroll
        for (int p = 0; p < 8; p++) {
            const int f = f0 + 8 * p;
            const size_t idx = base + (size_t)f * D_OUT + e;
            const float qv = g_q[idx];
            const float kv = g_k[idx];
            float sqv, cqv, skv, ckv;
            sincosf(qv, &sqv, &cqv);
            sincosf(kv, &skv, &ckv);
            cq[f * S2_PAD + e] = cqv * rw;
            sq[f * S2_PAD + e] = sqv * rw;
            ck[f * S2_PAD + e] = ckv;
            sk[f * S2_PAD + e] = skv;
            vv[f * S2_PAD + e] = g_v[idx];
        }
    }
    __syncthreads();

    {
        const int g   = tid & 63;
        const int fq0 = tid >> 6;
#pragma unroll 4
        for (int p = 0; p < 16; p++) {
            const int f = fq0 + 4 * p;
            float acc = 0.f;
#pragma unroll
            for (int e = 0; e < 32; e++) {
                acc = fmaf(cq[f * S2_PAD + e], ck[g * S2_PAD + e], acc);
                acc = fmaf(sq[f * S2_PAD + e], sk[g * S2_PAD + e], acc);
            }
            S[f * 64 + g] = 1.f / (1.f + __expf(-acc));
        }
    }
    __syncthreads();

    {
        const int d  = tid & 31;
        const int f0 = tid >> 5;
#pragma unroll
        for (int p = 0; p < 8; p++) {
            const int f = f0 + 8 * p;
            float acc = 0.f;
#pragma unroll
            for (int g = 0; g < 64; g++) {
                acc = fmaf(S[f * 64 + g], vv[g * S2_PAD + d], acc);
            }
            g_attn[base + (size_t)f * D_OUT + d] = acc;
        }
    }
}

// ---------------------------------------------------------------------------
// Stage 3b: LayerNorm(res + attn) -> out. One warp per row.
// ---------------------------------------------------------------------------
__global__ __launch_bounds__(256) void ln_kernel(
    const float* __restrict__ gamma, const float* __restrict__ beta,
    float* __restrict__ out)
{
    const int row  = blockIdx.x * 8 + (threadIdx.x >> 5);
    const int lane = threadIdx.x & 31;
    const size_t base = (size_t)row * D_OUT + lane * 8;

    float4 r0 = *reinterpret_cast<const float4*>(&g_res[base]);
    float4 r1 = *reinterpret_cast<const float4*>(&g_res[base + 4]);
    float4 a0 = *reinterpret_cast<const float4*>(&g_attn[base]);
    float4 a1 = *reinterpret_cast<const float4*>(&g_attn[base + 4]);

    float v[8];
    v[0] = r0.x + a0.x; v[1] = r0.y + a0.y; v[2] = r0.z + a0.z; v[3] = r0.w + a0.w;
    v[4] = r1.x + a1.x; v[5] = r1.y + a1.y; v[6] = r1.z + a1.z; v[7] = r1.w + a1.w;

    float s = 0.f, ss = 0.f;
#pragma unroll
    for (int i = 0; i < 8; i++) { s += v[i]; ss = fmaf(v[i], v[i], ss); }
#pragma unroll
    for (int o = 16; o > 0; o >>= 1) {
        s  += __shfl_xor_sync(0xffffffffu, s,  o);
        ss += __shfl_xor_sync(0xffffffffu, ss, o);
    }
    const float mu  = s * (1.f / 256.f);
    const float var = ss * (1.f / 256.f) - mu * mu;
    const float inv = rsqrtf(var + LN_EPS);

    float o8[8];
#pragma unroll
    for (int i = 0; i < 8; i++) {
        const float g = gamma[lane * 8 + i];
        const float bb = beta[lane * 8 + i];
        o8[i] = fmaf((v[i] - mu) * inv, g, bb);
    }
    *reinterpret_cast<float4*>(&out[base])     = make_float4(o8[0], o8[1], o8[2], o8[3]);
    *reinterpret_cast<float4*>(&out[base + 4]) = make_float4(o8[4], o8[5], o8[6], o8[7]);
}

// ---------------------------------------------------------------------------
// Launch
// ---------------------------------------------------------------------------
extern "C" void kernel_launch(void* const* d_in, const int* in_sizes, int n_in,
                              void* d_out, int out_size)
{
    const float* theta  = (const float*)d_in[0];
    const float* Qw     = (const float*)d_in[1];
    const float* Kw     = (const float*)d_in[2];
    const float* Vw     = (const float*)d_in[3];
    const float* W_lin  = (const float*)d_in[4];
    const float* rot_w  = (const float*)d_in[5];
    const float* gammap = (const float*)d_in[6];
    const float* betap  = (const float*)d_in[7];
    float* out = (float*)d_out;

    cudaFuncSetAttribute(attn_kernel,
                         cudaFuncAttributeMaxDynamicSharedMemorySize, S2_SMEM_BYTES);

    // Stage 0: operand splits / transposes
    split_theta_kernel<<<(B_SZ * F_NUM * D_IN / 4) / 256, 256>>>(theta);
    split_weights_kernel<<<dim3(64, 3, F_NUM), 256>>>(Qw, Kw, Vw);
    split_wlin_kernel<<<(D_OUT * D_IN) / 256, 256>>>(W_lin);

    // Stage 1: QKV GEMM (warp MMA, bf16 split precision)
    qkv_mma_kernel<<<dim3(B_SZ / 128, 768 / 128, F_NUM), 256>>>();

    // Stage 2: attention
    attn_kernel<<<B_SZ * H_NUM, 256, S2_SMEM_BYTES>>>(rot_w);

    // Stage 3: linear GEMM then LN(res + attn)
    lin_mma_kernel<<<dim3((B_SZ * F_NUM) / 128, D_OUT / 128), 256>>>();
    ln_kernel<<<(B_SZ * F_NUM) / 8, 256>>>(gammap, betap, out);
}

// round 17
// speedup vs baseline: 2.8050x; 1.6350x over previous
#include <cuda_runtime.h>
#include <cuda_bf16.h>
#include <math.h>
#include <stdint.h>

// Problem constants
#define B_SZ   1024
#define F_NUM  64
#define D_IN   256
#define D_OUT  256
#define H_NUM  8
#define DH     32
#define LN_EPS 1e-5f

// ---------------------------------------------------------------------------
// Device scratch
// ---------------------------------------------------------------------------
__device__ float g_q[B_SZ * F_NUM * D_OUT];
__device__ float g_k[B_SZ * F_NUM * D_OUT];
__device__ float g_v[B_SZ * F_NUM * D_OUT];
__device__ float g_attn[B_SZ * F_NUM * D_OUT];
__device__ float g_res[B_SZ * F_NUM * D_OUT];

// Split-precision bf16 operands.
__device__ __nv_bfloat16 g_Ah[(size_t)F_NUM * B_SZ * D_IN];   // theta f-major
__device__ __nv_bfloat16 g_Al[(size_t)F_NUM * B_SZ * D_IN];
__device__ __nv_bfloat16 g_Th[(size_t)B_SZ * F_NUM * D_IN];   // theta natural
__device__ __nv_bfloat16 g_Tl[(size_t)B_SZ * F_NUM * D_IN];
__device__ __nv_bfloat16 g_Bh[(size_t)F_NUM * 3 * D_OUT * D_IN]; // QKV [f][n][k]
__device__ __nv_bfloat16 g_Bl[(size_t)F_NUM * 3 * D_OUT * D_IN];
__device__ __nv_bfloat16 g_Wh[(size_t)D_OUT * D_IN];          // W_lin [n][k]
__device__ __nv_bfloat16 g_Wl[(size_t)D_OUT * D_IN];

// ---------------------------------------------------------------------------
// Warp-MMA helpers (sm_80-era PTX, valid at compute_103)
// ---------------------------------------------------------------------------
__device__ __forceinline__ uint32_t smem_u32(const void* p) {
    uint32_t a;
    asm("{ .reg .u64 t; cvta.to.shared.u64 t, %1; cvt.u32.u64 %0, t; }" : "=r"(a) : "l"(p));
    return a;
}
__device__ __forceinline__ void ldmx4(uint32_t* r, uint32_t addr) {
    asm volatile("ldmatrix.sync.aligned.m8n8.x4.shared.b16 {%0,%1,%2,%3}, [%4];"
                 : "=r"(r[0]), "=r"(r[1]), "=r"(r[2]), "=r"(r[3]) : "r"(addr));
}
__device__ __forceinline__ void mma16816(float* d, const uint32_t* a, const uint32_t* b) {
    asm volatile("mma.sync.aligned.m16n8k16.row.col.f32.bf16.bf16.f32 "
                 "{%0,%1,%2,%3}, {%4,%5,%6,%7}, {%8,%9}, {%0,%1,%2,%3};"
                 : "+f"(d[0]), "+f"(d[1]), "+f"(d[2]), "+f"(d[3])
                 : "r"(a[0]), "r"(a[1]), "r"(a[2]), "r"(a[3]), "r"(b[0]), "r"(b[1]));
}
__device__ __forceinline__ void cp16(uint32_t dst, const void* src) {
    uint64_t g;
    asm("cvta.to.global.u64 %0, %1;" : "=l"(g) : "l"(src));
    asm volatile("cp.async.cg.shared.global [%0], [%1], 16;" :: "r"(dst), "l"(g));
}
#define CP_COMMIT() asm volatile("cp.async.commit_group;" ::: "memory")
#define CP_WAIT(n)  asm volatile("cp.async.wait_group %0;" :: "n"(n) : "memory")

__device__ __forceinline__ void split1(float x, __nv_bfloat16& h, __nv_bfloat16& l) {
    h = __float2bfloat16(x);
    l = __float2bfloat16(x - __bfloat162float(h));
}
__device__ __forceinline__ void split_pack2(float a, float b, uint32_t& hi, uint32_t& lo) {
    __nv_bfloat16 ah, al, bh, bl;
    split1(a, ah, al); split1(b, bh, bl);
    hi = (uint32_t)__bfloat16_as_ushort(ah) | ((uint32_t)__bfloat16_as_ushort(bh) << 16);
    lo = (uint32_t)__bfloat16_as_ushort(al) | ((uint32_t)__bfloat16_as_ushort(bl) << 16);
}

#define PITCH 40   // bf16 elems per smem row (80 B): conflict-free, 16B-aligned

// ---------------------------------------------------------------------------
// Stage 0a: split theta -> f-major hi/lo AND natural-layout hi/lo
// ---------------------------------------------------------------------------
__global__ __launch_bounds__(256) void split_theta_kernel(const float* __restrict__ theta)
{
    const size_t idx  = (size_t)blockIdx.x * blockDim.x + threadIdx.x;
    const size_t elem = idx * 4;
    const int d = (int)(elem & 255);
    const int f = (int)((elem >> 8) & 63);
    const int b = (int)(elem >> 14);
    float4 t4 = *reinterpret_cast<const float4*>(theta + elem);
    float xs[4] = {t4.x, t4.y, t4.z, t4.w};
    __nv_bfloat16 hi[4], lo[4];
#pragma unroll
    for (int i = 0; i < 4; i++) split1(xs[i], hi[i], lo[i]);
    const size_t o = ((size_t)f << 18) + ((size_t)b << 8) + d;
    *reinterpret_cast<uint2*>(&g_Ah[o]) = *reinterpret_cast<uint2*>(hi);
    *reinterpret_cast<uint2*>(&g_Al[o]) = *reinterpret_cast<uint2*>(lo);
    *reinterpret_cast<uint2*>(&g_Th[elem]) = *reinterpret_cast<uint2*>(hi);
    *reinterpret_cast<uint2*>(&g_Tl[elem]) = *reinterpret_cast<uint2*>(lo);
}

// ---------------------------------------------------------------------------
// Stage 0b: transpose + split QKV weights: W[f][d][w] -> B[f][which*256+w][d]
// ---------------------------------------------------------------------------
__global__ __launch_bounds__(256) void split_weights_kernel(
    const float* __restrict__ Qw, const float* __restrict__ Kw, const float* __restrict__ Vw)
{
    __shared__ float tile[32][33];
    const int f = blockIdx.z;
    const int which = blockIdx.y;
    const int d0 = (blockIdx.x >> 3) * 32;
    const int w0 = (blockIdx.x & 7) * 32;
    const float* W = (which == 0 ? Qw : (which == 1 ? Kw : Vw)) + (size_t)f * D_IN * D_OUT;

    const int c = threadIdx.x & 31;
    const int r0 = threadIdx.x >> 5;
#pragma unroll
    for (int i = 0; i < 4; i++) {
        const int r = r0 + 8 * i;
        tile[r][c] = W[(size_t)(d0 + r) * D_OUT + w0 + c];
    }
    __syncthreads();

    const size_t outbase = (size_t)f * (3 * D_OUT * D_IN) + (size_t)(which * 256 + w0) * D_IN + d0;
#pragma unroll
    for (int i = 0; i < 4; i++) {
        const int wr = r0 + 8 * i;
        const int dc = c;
        __nv_bfloat16 hi, lo;
        split1(tile[dc][wr], hi, lo);
        g_Bh[outbase + (size_t)wr * D_IN + dc] = hi;
        g_Bl[outbase + (size_t)wr * D_IN + dc] = lo;
    }
}

// ---------------------------------------------------------------------------
// Stage 0c: split W_lin elementwise (already [N][K] K-major)
// ---------------------------------------------------------------------------
__global__ __launch_bounds__(256) void split_wlin_kernel(const float* __restrict__ W_lin)
{
    const int i = blockIdx.x * blockDim.x + threadIdx.x;
    __nv_bfloat16 hi, lo;
    split1(W_lin[i], hi, lo);
    g_Wh[i] = hi;
    g_Wl[i] = lo;
}

// ---------------------------------------------------------------------------
// cp.async double-buffered mainloop (CTA 128x128, BK=32, 8 warps).
// acc = Ah*Bh + Ah*Bl + Al*Bh over K=256.
// ---------------------------------------------------------------------------
struct SmemStage {
    __nv_bfloat16 Ah[128 * PITCH];
    __nv_bfloat16 Al[128 * PITCH];
    __nv_bfloat16 Bh[128 * PITCH];
    __nv_bfloat16 Bl[128 * PITCH];
};

// Decode: 128 rows x 4 chunks of 8 elems (BK=32). 512 slots over 256 threads
// -> 2 iterations. Max smem elem offset = 127*40 + 24 + 8 = 5112 < 5120. OK.
__device__ __forceinline__ void copy_stage(SmemStage& st,
    const __nv_bfloat16* gAh, const __nv_bfloat16* gAl,
    const __nv_bfloat16* gBh, const __nv_bfloat16* gBl, int k0, int tid)
{
#pragma unroll
    for (int j = 0; j < 2; j++) {
        const int c = tid + 256 * j;                  // 0..511
        const int row = c >> 2;                       // 0..127
        const int col8 = (c & 3) * 8;                 // 0,8,16,24
        const int soff = row * PITCH + col8;
        const size_t goff = (size_t)row * 256 + k0 + col8;
        cp16(smem_u32(&st.Ah[soff]), gAh + goff);
        cp16(smem_u32(&st.Al[soff]), gAl + goff);
        cp16(smem_u32(&st.Bh[soff]), gBh + goff);
        cp16(smem_u32(&st.Bl[soff]), gBl + goff);
    }
}

__device__ __forceinline__ void mma_mainloop(SmemStage* stg,
    const __nv_bfloat16* __restrict__ gAh, const __nv_bfloat16* __restrict__ gAl,
    const __nv_bfloat16* __restrict__ gBh, const __nv_bfloat16* __restrict__ gBl,
    float acc[4][4][4])
{
    const int tid = threadIdx.x;
    const int lane = tid & 31;
    const int wid = tid >> 5;
    const int warp_m = wid & 1;
    const int warp_n = wid >> 1;

    const int a_row = warp_m * 64 + (lane & 15);
    const int a_kh  = (lane >> 4) << 3;
    const int b_n   = warp_n * 32 + (lane & 7) + ((lane >> 4) << 3);
    const int b_kh  = ((lane >> 3) & 1) << 3;

    copy_stage(stg[0], gAh, gAl, gBh, gBl, 0, tid);
    CP_COMMIT();

    for (int kt = 0; kt < 8; kt++) {
        if (kt < 7) {
            copy_stage(stg[(kt + 1) & 1], gAh, gAl, gBh, gBl, (kt + 1) * 32, tid);
            CP_COMMIT();
            CP_WAIT(1);
        } else {
            CP_WAIT(0);
        }
        __syncthreads();

        SmemStage& sm = stg[kt & 1];
#pragma unroll
        for (int kh = 0; kh < 2; kh++) {
            const int k16 = kh * 16;
            uint32_t bh[4][2], bl[4][2];
#pragma unroll
            for (int p = 0; p < 2; p++) {
                uint32_t r[4];
                const int nrow = b_n + p * 16;
                ldmx4(r, smem_u32(&sm.Bh[nrow * PITCH + k16 + b_kh]));
                bh[2 * p][0] = r[0]; bh[2 * p][1] = r[1];
                bh[2 * p + 1][0] = r[2]; bh[2 * p + 1][1] = r[3];
                ldmx4(r, smem_u32(&sm.Bl[nrow * PITCH + k16 + b_kh]));
                bl[2 * p][0] = r[0]; bl[2 * p][1] = r[1];
                bl[2 * p + 1][0] = r[2]; bl[2 * p + 1][1] = r[3];
            }
#pragma unroll
            for (int mf = 0; mf < 4; mf++) {
                uint32_t ah[4], al[4];
                const int arow = a_row + mf * 16;
                ldmx4(ah, smem_u32(&sm.Ah[arow * PITCH + k16 + a_kh]));
                ldmx4(al, smem_u32(&sm.Al[arow * PITCH + k16 + a_kh]));
#pragma unroll
                for (int nf = 0; nf < 4; nf++) {
                    mma16816(acc[mf][nf], ah, bh[nf]);
                    mma16816(acc[mf][nf], ah, bl[nf]);
                    mma16816(acc[mf][nf], al, bh[nf]);
                }
            }
        }
        __syncthreads();
    }
}

// ---------------------------------------------------------------------------
// Stage 1: QKV GEMM. grid (8, 6, 64)
// ---------------------------------------------------------------------------
__global__ __launch_bounds__(256, 2) void qkv_mma_kernel()
{
    extern __shared__ __align__(16) char qsm[];
    SmemStage* stg = reinterpret_cast<SmemStage*>(qsm);
    const int lane = threadIdx.x & 31;
    const int wid  = threadIdx.x >> 5;
    const int warp_m = wid & 1, warp_n = wid >> 1;
    const int f  = blockIdx.z;
    const int m0 = blockIdx.x * 128;
    const int n0 = blockIdx.y * 128;

    const __nv_bfloat16* gAh = g_Ah + ((size_t)f << 18) + ((size_t)m0 << 8);
    const __nv_bfloat16* gAl = g_Al + ((size_t)f << 18) + ((size_t)m0 << 8);
    const __nv_bfloat16* gBh = g_Bh + (size_t)f * (3 * D_OUT * D_IN) + ((size_t)n0 << 8);
    const __nv_bfloat16* gBl = g_Bl + (size_t)f * (3 * D_OUT * D_IN) + ((size_t)n0 << 8);

    float acc[4][4][4];
#pragma unroll
    for (int a = 0; a < 4; a++)
#pragma unroll
        for (int b = 0; b < 4; b++)
#pragma unroll
            for (int c = 0; c < 4; c++) acc[a][b][c] = 0.f;

    mma_mainloop(stg, gAh, gAl, gBh, gBl, acc);

    const int gn = n0 + warp_n * 32;
    const int which = gn >> 8;
    float* C = (which == 0 ? g_q : (which == 1 ? g_k : g_v));
    const int wloc = gn & 255;
#pragma unroll
    for (int mf = 0; mf < 4; mf++) {
        const int row = m0 + warp_m * 64 + mf * 16 + (lane >> 2);
#pragma unroll
        for (int nf = 0; nf < 4; nf++) {
            const int c = wloc + nf * 8 + (lane & 3) * 2;
            const size_t o = (size_t)row * (F_NUM * D_OUT) + f * 256 + c;
            *reinterpret_cast<float2*>(&C[o]) = make_float2(acc[mf][nf][0], acc[mf][nf][1]);
            *reinterpret_cast<float2*>(&C[o + (size_t)8 * (F_NUM * D_OUT)]) =
                make_float2(acc[mf][nf][2], acc[mf][nf][3]);
        }
    }
}

// ---------------------------------------------------------------------------
// Stage 3a: linear GEMM res = theta @ W_lin^T. grid (512, 2)
// ---------------------------------------------------------------------------
__global__ __launch_bounds__(256, 2) void lin_mma_kernel()
{
    extern __shared__ __align__(16) char qsm[];
    SmemStage* stg = reinterpret_cast<SmemStage*>(qsm);
    const int lane = threadIdx.x & 31;
    const int wid  = threadIdx.x >> 5;
    const int warp_m = wid & 1, warp_n = wid >> 1;
    const int m0 = blockIdx.x * 128;
    const int n0 = blockIdx.y * 128;

    float acc[4][4][4];
#pragma unroll
    for (int a = 0; a < 4; a++)
#pragma unroll
        for (int b = 0; b < 4; b++)
#pragma unroll
            for (int c = 0; c < 4; c++) acc[a][b][c] = 0.f;

    mma_mainloop(stg, g_Th + ((size_t)m0 << 8), g_Tl + ((size_t)m0 << 8),
                 g_Wh + ((size_t)n0 << 8), g_Wl + ((size_t)n0 << 8), acc);

#pragma unroll
    for (int mf = 0; mf < 4; mf++) {
        const int row = m0 + warp_m * 64 + mf * 16 + (lane >> 2);
#pragma unroll
        for (int nf = 0; nf < 4; nf++) {
            const int c = n0 + warp_n * 32 + nf * 8 + (lane & 3) * 2;
            const size_t o = (size_t)row * D_OUT + c;
            *reinterpret_cast<float2*>(&g_res[o]) = make_float2(acc[mf][nf][0], acc[mf][nf][1]);
            *reinterpret_cast<float2*>(&g_res[o + (size_t)8 * D_OUT]) =
                make_float2(acc[mf][nf][2], acc[mf][nf][3]);
        }
    }
}

// ---------------------------------------------------------------------------
// Stage 2: tensor-core attention. Block = 256 threads = 2 heads (128 thr each).
// logits via split-bf16 trig MMAs; sigmoid in regs; C-frag -> A-frag reuse
// for S@V with V^T staged hi/lo in smem.
// ---------------------------------------------------------------------------
#define APITCH 40
#define VPITCH 72
struct AttnSmem {
    __nv_bfloat16 cqh[64 * APITCH], cql[64 * APITCH];
    __nv_bfloat16 sqh[64 * APITCH], sql[64 * APITCH];
    __nv_bfloat16 ckh[64 * APITCH], ckl[64 * APITCH];
    __nv_bfloat16 skh[64 * APITCH], skl[64 * APITCH];
    __nv_bfloat16 vth[32 * VPITCH], vtl[32 * VPITCH];
};
#define ATTN_SMEM (2 * (int)sizeof(AttnSmem))

__global__ __launch_bounds__(256, 2) void attn_tc_kernel(const float* __restrict__ rot_w)
{
    extern __shared__ __align__(16) char smraw[];
    AttnSmem* heads = reinterpret_cast<AttnSmem*>(smraw);
    const int tid = threadIdx.x;
    const int wg = tid >> 7;
    const int wg_tid = tid & 127;
    const int lane = tid & 31;
    const int warp_m = (tid >> 5) & 3;
    AttnSmem& S = heads[wg];

    const int head_id = blockIdx.x * 2 + wg;
    const int b = head_id >> 3;
    const int h = head_id & 7;
    const size_t base = (size_t)b * (F_NUM * D_OUT) + (size_t)h * DH;

    // Phase 1: load q/k/v, trig, split, stage to smem (V transposed).
    {
        const int e4 = (wg_tid & 7) * 4;
        float4 rw4 = *reinterpret_cast<const float4*>(rot_w + e4);
        float rw[4] = {rw4.x, rw4.y, rw4.z, rw4.w};
#pragma unroll
        for (int i = 0; i < 4; i++) {
            const int f = (wg_tid + 128 * i) >> 3;
            const size_t g = base + (size_t)f * D_OUT + e4;
            float4 q4 = *reinterpret_cast<const float4*>(g_q + g);
            float4 k4 = *reinterpret_cast<const float4*>(g_k + g);
            float4 v4 = *reinterpret_cast<const float4*>(g_v + g);
            float qa[4] = {q4.x, q4.y, q4.z, q4.w};
            float ka[4] = {k4.x, k4.y, k4.z, k4.w};
            float va[4] = {v4.x, v4.y, v4.z, v4.w};
            uint32_t pcqh[2], pcql[2], psqh[2], psql[2];
            uint32_t pckh[2], pckl[2], pskh[2], pskl[2];
#pragma unroll
            for (int p = 0; p < 2; p++) {
                float sq0, cq0, sq1, cq1, sk0, ck0, sk1, ck1;
                sincosf(qa[2 * p], &sq0, &cq0);
                sincosf(qa[2 * p + 1], &sq1, &cq1);
                sincosf(ka[2 * p], &sk0, &ck0);
                sincosf(ka[2 * p + 1], &sk1, &ck1);
                split_pack2(cq0 * rw[2 * p], cq1 * rw[2 * p + 1], pcqh[p], pcql[p]);
                split_pack2(sq0 * rw[2 * p], sq1 * rw[2 * p + 1], psqh[p], psql[p]);
                split_pack2(ck0, ck1, pckh[p], pckl[p]);
                split_pack2(sk0, sk1, pskh[p], pskl[p]);
                __nv_bfloat16 vh0, vl0, vh1, vl1;
                split1(va[2 * p], vh0, vl0);
                split1(va[2 * p + 1], vh1, vl1);
                S.vth[(e4 + 2 * p) * VPITCH + f] = vh0;
                S.vtl[(e4 + 2 * p) * VPITCH + f] = vl0;
                S.vth[(e4 + 2 * p + 1) * VPITCH + f] = vh1;
                S.vtl[(e4 + 2 * p + 1) * VPITCH + f] = vl1;
            }
            const int so = f * APITCH + e4;
            *reinterpret_cast<uint2*>(&S.cqh[so]) = make_uint2(pcqh[0], pcqh[1]);
            *reinterpret_cast<uint2*>(&S.cql[so]) = make_uint2(pcql[0], pcql[1]);
            *reinterpret_cast<uint2*>(&S.sqh[so]) = make_uint2(psqh[0], psqh[1]);
            *reinterpret_cast<uint2*>(&S.sql[so]) = make_uint2(psql[0], psql[1]);
            *reinterpret_cast<uint2*>(&S.ckh[so]) = make_uint2(pckh[0], pckh[1]);
            *reinterpret_cast<uint2*>(&S.ckl[so]) = make_uint2(pckl[0], pckl[1]);
            *reinterpret_cast<uint2*>(&S.skh[so]) = make_uint2(pskh[0], pskh[1]);
            *reinterpret_cast<uint2*>(&S.skl[so]) = make_uint2(pskl[0], pskl[1]);
        }
    }
    __syncthreads();

    // Phase 2: logits (warp computes m16 x n64, K=32; 6 split-MMA combos).
    const int m0 = warp_m * 16;
    float c[8][4];
#pragma unroll
    for (int j = 0; j < 8; j++)
#pragma unroll
        for (int r = 0; r < 4; r++) c[j][r] = 0.f;

#pragma unroll
    for (int kh = 0; kh < 2; kh++) {
        const int aoff = (m0 + (lane & 15)) * APITCH + kh * 16 + ((lane >> 4) << 3);
        uint32_t ach[4], acl[4], ash[4], asl[4];
        ldmx4(ach, smem_u32(&S.cqh[aoff]));
        ldmx4(acl, smem_u32(&S.cql[aoff]));
        ldmx4(ash, smem_u32(&S.sqh[aoff]));
        ldmx4(asl, smem_u32(&S.sql[aoff]));
#pragma unroll
        for (int n16 = 0; n16 < 4; n16++) {
            const int boff = (n16 * 16 + (lane & 7) + ((lane >> 4) << 3)) * APITCH
                           + kh * 16 + (((lane >> 3) & 1) << 3);
            uint32_t bch[4], bcl[4], bsh[4], bsl[4];
            ldmx4(bch, smem_u32(&S.ckh[boff]));
            ldmx4(bcl, smem_u32(&S.ckl[boff]));
            ldmx4(bsh, smem_u32(&S.skh[boff]));
            ldmx4(bsl, smem_u32(&S.skl[boff]));
#pragma unroll
            for (int p = 0; p < 2; p++) {
                float* cc = c[n16 * 2 + p];
                mma16816(cc, ach, bch + 2 * p);
                mma16816(cc, ach, bcl + 2 * p);
                mma16816(cc, acl, bch + 2 * p);
                mma16816(cc, ash, bsh + 2 * p);
                mma16816(cc, ash, bsl + 2 * p);
                mma16816(cc, asl, bsh + 2 * p);
            }
        }
    }

    // Phase 3: sigmoid + repack C-frags as A-frags (hi/lo) for S@V.
#pragma unroll
    for (int j = 0; j < 8; j++)
#pragma unroll
        for (int r = 0; r < 4; r++)
            c[j][r] = 1.f / (1.f + __expf(-c[j][r]));

    uint32_t sh_[4][4], sl_[4][4];
#pragma unroll
    for (int g = 0; g < 4; g++) {
        split_pack2(c[2 * g][0],     c[2 * g][1],     sh_[g][0], sl_[g][0]);
        split_pack2(c[2 * g][2],     c[2 * g][3],     sh_[g][1], sl_[g][1]);
        split_pack2(c[2 * g + 1][0], c[2 * g + 1][1], sh_[g][2], sl_[g][2]);
        split_pack2(c[2 * g + 1][2], c[2 * g + 1][3], sh_[g][3], sl_[g][3]);
    }

    // Phase 4: out(m16 x n32) = S(16x64) @ V(64x32), K=64 in 4 k16 steps.
    float o[4][4];
#pragma unroll
    for (int t = 0; t < 4; t++)
#pragma unroll
        for (int r = 0; r < 4; r++) o[t][r] = 0.f;

#pragma unroll
    for (int g = 0; g < 4; g++) {
#pragma unroll
        for (int n16 = 0; n16 < 2; n16++) {
            const int boff = (n16 * 16 + (lane & 7) + ((lane >> 4) << 3)) * VPITCH
                           + g * 16 + (((lane >> 3) & 1) << 3);
            uint32_t bvh[4], bvl[4];
            ldmx4(bvh, smem_u32(&S.vth[boff]));
            ldmx4(bvl, smem_u32(&S.vtl[boff]));
#pragma unroll
            for (int p = 0; p < 2; p++) {
                float* oo = o[n16 * 2 + p];
                mma16816(oo, sh_[g], bvh + 2 * p);
                mma16816(oo, sh_[g], bvl + 2 * p);
                mma16816(oo, sl_[g], bvh + 2 * p);
            }
        }
    }

    // Phase 5: store out -> g_attn[b, f, h*32 + d]
    const int r = lane >> 2;
    const int cp2 = (lane & 3) * 2;
#pragma unroll
    for (int t = 0; t < 4; t++) {
        const size_t o0 = base + (size_t)(m0 + r) * D_OUT + t * 8 + cp2;
        *reinterpret_cast<float2*>(&g_attn[o0]) = make_float2(o[t][0], o[t][1]);
        *reinterpret_cast<float2*>(&g_attn[o0 + (size_t)8 * D_OUT]) =
            make_float2(o[t][2], o[t][3]);
    }
}

// ---------------------------------------------------------------------------
// Stage 3b: LayerNorm(res + attn) -> out. One warp per row.
// ---------------------------------------------------------------------------
__global__ __launch_bounds__(256) void ln_kernel(
    const float* __restrict__ gamma, const float* __restrict__ beta,
    float* __restrict__ out)
{
    const int row  = blockIdx.x * 8 + (threadIdx.x >> 5);
    const int lane = threadIdx.x & 31;
    const size_t base = (size_t)row * D_OUT + lane * 8;

    float4 r0 = *reinterpret_cast<const float4*>(&g_res[base]);
    float4 r1 = *reinterpret_cast<const float4*>(&g_res[base + 4]);
    float4 a0 = *reinterpret_cast<const float4*>(&g_attn[base]);
    float4 a1 = *reinterpret_cast<const float4*>(&g_attn[base + 4]);

    float v[8];
    v[0] = r0.x + a0.x; v[1] = r0.y + a0.y; v[2] = r0.z + a0.z; v[3] = r0.w + a0.w;
    v[4] = r1.x + a1.x; v[5] = r1.y + a1.y; v[6] = r1.z + a1.z; v[7] = r1.w + a1.w;

    float s = 0.f, ss = 0.f;
#pragma unroll
    for (int i = 0; i < 8; i++) { s += v[i]; ss = fmaf(v[i], v[i], ss); }
#pragma unroll
    for (int o = 16; o > 0; o >>= 1) {
        s  += __shfl_xor_sync(0xffffffffu, s,  o);
        ss += __shfl_xor_sync(0xffffffffu, ss, o);
    }
    const float mu  = s * (1.f / 256.f);
    const float var = ss * (1.f / 256.f) - mu * mu;
    const float inv = rsqrtf(var + LN_EPS);

    float o8[8];
#pragma unroll
    for (int i = 0; i < 8; i++) {
        o8[i] = fmaf((v[i] - mu) * inv, gamma[lane * 8 + i], beta[lane * 8 + i]);
    }
    *reinterpret_cast<float4*>(&out[base])     = make_float4(o8[0], o8[1], o8[2], o8[3]);
    *reinterpret_cast<float4*>(&out[base + 4]) = make_float4(o8[4], o8[5], o8[6], o8[7]);
}

// ---------------------------------------------------------------------------
// Launch
// ---------------------------------------------------------------------------
extern "C" void kernel_launch(void* const* d_in, const int* in_sizes, int n_in,
                              void* d_out, int out_size)
{
    const float* theta  = (const float*)d_in[0];
    const float* Qw     = (const float*)d_in[1];
    const float* Kw     = (const float*)d_in[2];
    const float* Vw     = (const float*)d_in[3];
    const float* W_lin  = (const float*)d_in[4];
    const float* rot_w  = (const float*)d_in[5];
    const float* gammap = (const float*)d_in[6];
    const float* betap  = (const float*)d_in[7];
    float* out = (float*)d_out;

    const int gemm_smem = 2 * (int)sizeof(SmemStage);   // 81920
    cudaFuncSetAttribute(qkv_mma_kernel,
                         cudaFuncAttributeMaxDynamicSharedMemorySize, gemm_smem);
    cudaFuncSetAttribute(lin_mma_kernel,
                         cudaFuncAttributeMaxDynamicSharedMemorySize, gemm_smem);
    cudaFuncSetAttribute(attn_tc_kernel,
                         cudaFuncAttributeMaxDynamicSharedMemorySize, ATTN_SMEM);

    // Stage 0: operand splits / transposes
    split_theta_kernel<<<(B_SZ * F_NUM * D_IN / 4) / 256, 256>>>(theta);
    split_weights_kernel<<<dim3(64, 3, F_NUM), 256>>>(Qw, Kw, Vw);
    split_wlin_kernel<<<(D_OUT * D_IN) / 256, 256>>>(W_lin);

    // Stage 1: QKV GEMM (warp MMA + cp.async double buffering)
    qkv_mma_kernel<<<dim3(B_SZ / 128, 768 / 128, F_NUM), 256, gemm_smem>>>();

    // Stage 2: tensor-core attention
    attn_tc_kernel<<<(B_SZ * H_NUM) / 2, 256, ATTN_SMEM>>>(rot_w);

    // Stage 3: linear GEMM then LN(res + attn)
    lin_mma_kernel<<<dim3((B_SZ * F_NUM) / 128, D_OUT / 128), 256, gemm_smem>>>();
    ln_kernel<<<(B_SZ * F_NUM) / 8, 256>>>(gammap, betap, out);
}